// round 7
// baseline (speedup 1.0000x reference)
#include <cuda_runtime.h>
#include <cuda_bf16.h>
#include <cstdint>

#define N_NODES 100000
#define N_EDGES 1000000
#define IN_CH   32
#define EDGE_CH 16
#define OUT_CH  32
#define D_MID   56
#define D_CAT   80
#define TILE_E  64

typedef unsigned int u32;

// ---- device globals (no allocation allowed) --------------------------------
static __device__ int g_is64;
static __device__ __align__(16) __nv_bfloat16 g_xhi[N_NODES * IN_CH];
static __device__ __align__(16) __nv_bfloat16 g_xlo[N_NODES * IN_CH];
static __device__ __align__(16) __nv_bfloat16 g_w1hi[D_MID * 88];  // [n][k], stride 88
static __device__ __align__(16) __nv_bfloat16 g_w1lo[D_MID * 88];
static __device__ __align__(16) __nv_bfloat16 g_w2hi[OUT_CH * 64]; // [n][k], k padded 56->64
static __device__ __align__(16) __nv_bfloat16 g_w2lo[OUT_CH * 64];

// ---- helpers ---------------------------------------------------------------
__device__ __forceinline__ void atomicMaxF(float* addr, float val) {
    if (val >= 0.0f) atomicMax(reinterpret_cast<int*>(addr), __float_as_int(val));
    else             atomicMin(reinterpret_cast<unsigned int*>(addr), __float_as_uint(val));
}

__device__ __forceinline__ void mma16816(float d[4], const u32 a[4], u32 b0, u32 b1) {
    asm volatile(
        "mma.sync.aligned.m16n8k16.row.col.f32.bf16.bf16.f32 "
        "{%0,%1,%2,%3}, {%4,%5,%6,%7}, {%8,%9}, {%0,%1,%2,%3};\n"
        : "+f"(d[0]), "+f"(d[1]), "+f"(d[2]), "+f"(d[3])
        : "r"(a[0]), "r"(a[1]), "r"(a[2]), "r"(a[3]), "r"(b0), "r"(b1));
}

// split (v0,v1) into packed bf16x2 hi (return) and lo (out-param)
__device__ __forceinline__ u32 pack_split(float v0, float v1, u32& lo) {
    __nv_bfloat16 h0 = __float2bfloat16(v0), h1 = __float2bfloat16(v1);
    float f0 = __bfloat162float(h0), f1 = __bfloat162float(h1);
    __nv_bfloat16 l0 = __float2bfloat16(v0 - f0), l1 = __float2bfloat16(v1 - f1);
    lo = (u32)__bfloat16_as_ushort(l0) | ((u32)__bfloat16_as_ushort(l1) << 16);
    return (u32)__bfloat16_as_ushort(h0) | ((u32)__bfloat16_as_ushort(h1) << 16);
}

// ---------------------------------------------------------------------------
// K0: init out to -inf, detect int64, prepack x / W1 / W2 into bf16 hi/lo
// ---------------------------------------------------------------------------
__global__ void k_pre(const float* __restrict__ x,
                      const unsigned int* __restrict__ widx,
                      const float* __restrict__ W1,
                      const float* __restrict__ W2,
                      unsigned int* __restrict__ out) {
    if (blockIdx.x == 0) {
        __shared__ int bad;
        if (threadIdx.x == 0) bad = 0;
        __syncthreads();
        for (int i = threadIdx.x; i < 4096; i += blockDim.x)
            if (widx[2 * i + 1] != 0u) bad = 1;   // benign race
        __syncthreads();
        if (threadIdx.x == 0) g_is64 = !bad;
    }
    if (blockIdx.x == 1) {  // W1 [80][56] -> [n][k] hi/lo, stride 88
        for (int i = threadIdx.x; i < D_CAT * D_MID; i += blockDim.x) {
            int k = i / D_MID, n = i % D_MID;
            float v = W1[i];
            __nv_bfloat16 h = __float2bfloat16(v);
            g_w1hi[n * 88 + k] = h;
            g_w1lo[n * 88 + k] = __float2bfloat16(v - __bfloat162float(h));
        }
    }
    if (blockIdx.x == 2) {  // W2 [56][32] -> [n][k pad 64] hi/lo
        for (int i = threadIdx.x; i < OUT_CH * 64; i += blockDim.x) {
            int n = i / 64, k = i % 64;
            float v = (k < D_MID) ? W2[k * OUT_CH + n] : 0.0f;
            __nv_bfloat16 h = __float2bfloat16(v);
            g_w2hi[n * 64 + k] = h;
            g_w2lo[n * 64 + k] = __float2bfloat16(v - __bfloat162float(h));
        }
    }
    int stride = gridDim.x * blockDim.x;
    for (int i = blockIdx.x * blockDim.x + threadIdx.x; i < N_NODES * IN_CH; i += stride) {
        out[i] = 0xFF800000u;  // -inf
        float v = x[i];
        __nv_bfloat16 h = __float2bfloat16(v);
        g_xhi[i] = h;
        g_xlo[i] = __float2bfloat16(v - __bfloat162float(h));
    }
}

// ---------------------------------------------------------------------------
// K1: tensor-core edge MLP + scatter-max.  Block = 64 edges, 4 warps x 16 rows.
// smem word map: A_hi[64x44]@0, A_lo@2816, W1_hi[56x44]@5632, W1_lo@8096.
// H (64x36 words, stride 36) reuses A region after a block-wide sync.
// ---------------------------------------------------------------------------
#define A_HI  0
#define A_LO  2816
#define W1_HI 5632
#define W1_LO 8096
#define SMW   10560

__global__ void __launch_bounds__(128) k_edge(const int* __restrict__ idx32,
                                              const float* __restrict__ ea,
                                              const float* __restrict__ b1,
                                              const float* __restrict__ b2,
                                              float* __restrict__ out) {
    __shared__ u32 sm[SMW];
    __shared__ int srol[TILE_E], scol[TILE_E];

    const int tid  = threadIdx.x;
    const int w    = tid >> 5;
    const int lane = tid & 31;
    const int g    = lane >> 2;   // groupID 0..7
    const int t    = lane & 3;    // threadIdInGroup
    const int ebase = blockIdx.x * TILE_E;

    // edge indices
    if (tid < TILE_E) {
        int e = ebase + tid;
        if (e > N_EDGES - 1) e = N_EDGES - 1;
        int r, c;
        if (g_is64) { r = idx32[2 * e];  c = idx32[2 * (N_EDGES + e)]; }
        else        { r = idx32[e];      c = idx32[N_EDGES + e]; }
        srol[tid] = r; scol[tid] = c;
    }
    // W1 tiles into smem (prepacked)
    {
        const u32* g1h = reinterpret_cast<const u32*>(g_w1hi);
        const u32* g1l = reinterpret_cast<const u32*>(g_w1lo);
        for (int i = tid; i < D_MID * 44; i += 128) {
            sm[W1_HI + i] = g1h[i];
            sm[W1_LO + i] = g1l[i];
        }
    }
    __syncthreads();

    // gather x rows (prepacked bf16): 256 row-copies x 4 float4 quads
#pragma unroll
    for (int j = 0; j < 8; j++) {
        int task  = j * 128 + tid;
        int quad  = task & 3;
        int rowid = task >> 2;       // 0..255
        int e     = rowid & 63;
        int sel   = rowid >> 6;      // 0:hi-rol 1:hi-col 2:lo-rol 3:lo-col
        int node  = (sel & 1) ? scol[e] : srol[e];
        const float4* src = reinterpret_cast<const float4*>(
            ((sel < 2) ? g_xhi : g_xlo) + (size_t)node * IN_CH) + quad;
        float4 v = *src;
        u32 off = ((sel < 2) ? A_HI : A_LO) + e * 44 + (sel & 1) * 16 + quad * 4;
        *reinterpret_cast<float4*>(sm + off) = v;
    }
    // edge_attr -> bf16 hi/lo (k cols 64..79)
    {
        __nv_bfloat16* smh = reinterpret_cast<__nv_bfloat16*>(sm);
#pragma unroll
        for (int i = 0; i < 8; i++) {
            int li  = tid + 128 * i;   // 0..1023
            int el  = li >> 4, pos = li & 15;
            float v = (ebase + el < N_EDGES) ? ea[(size_t)(ebase + el) * EDGE_CH + pos] : 0.0f;
            __nv_bfloat16 h = __float2bfloat16(v);
            smh[(u32)(A_HI * 2) + el * 88 + 64 + pos] = h;
            smh[(u32)(A_LO * 2) + el * 88 + 64 + pos] =
                __float2bfloat16(v - __bfloat162float(h));
        }
    }
    __syncthreads();

    // ---- layer 1: H[64x56] = A[64x80] @ W1 + b1  (3-pass split mma) ----
    float acc[7][4];
#pragma unroll
    for (int nt = 0; nt < 7; nt++) {
        float bb0 = __ldg(&b1[nt * 8 + 2 * t]);
        float bb1 = __ldg(&b1[nt * 8 + 2 * t + 1]);
        acc[nt][0] = bb0; acc[nt][1] = bb1; acc[nt][2] = bb0; acc[nt][3] = bb1;
    }
    {
        const int ar0 = (w * 16 + g) * 44;
        const int ar1 = (w * 16 + g + 8) * 44;
#pragma unroll
        for (int ks = 0; ks < 5; ks++) {
            int c0 = ks * 8 + t, c1 = c0 + 4;
            u32 ahi[4], alo[4];
            ahi[0] = sm[A_HI + ar0 + c0]; ahi[1] = sm[A_HI + ar1 + c0];
            ahi[2] = sm[A_HI + ar0 + c1]; ahi[3] = sm[A_HI + ar1 + c1];
            alo[0] = sm[A_LO + ar0 + c0]; alo[1] = sm[A_LO + ar1 + c0];
            alo[2] = sm[A_LO + ar0 + c1]; alo[3] = sm[A_LO + ar1 + c1];
#pragma unroll
            for (int nt = 0; nt < 7; nt++) {
                int bro = (nt * 8 + g) * 44 + ks * 8 + t;
                u32 bh0 = sm[W1_HI + bro], bh1 = sm[W1_HI + bro + 4];
                u32 bl0 = sm[W1_LO + bro], bl1 = sm[W1_LO + bro + 4];
                mma16816(acc[nt], ahi, bh0, bh1);
                mma16816(acc[nt], ahi, bl0, bl1);
                mma16816(acc[nt], alo, bh0, bh1);
            }
        }
    }
    __syncthreads();  // everyone done reading A before H overwrites it

    // ---- LeakyReLU(H) -> bf16 hi/lo into smem (stride 36 words) ----
    {
        const int hr0 = (w * 16 + g) * 36;
        const int hr1 = (w * 16 + g + 8) * 36;
#pragma unroll
        for (int nt = 0; nt < 7; nt++) {
            float v0 = acc[nt][0], v1 = acc[nt][1], v2 = acc[nt][2], v3 = acc[nt][3];
            v0 = fmaxf(v0, 0.01f * v0); v1 = fmaxf(v1, 0.01f * v1);
            v2 = fmaxf(v2, 0.01f * v2); v3 = fmaxf(v3, 0.01f * v3);
            u32 lo, hi;
            hi = pack_split(v0, v1, lo);
            sm[A_HI + hr0 + nt * 4 + t] = hi;
            sm[A_LO + hr0 + nt * 4 + t] = lo;
            hi = pack_split(v2, v3, lo);
            sm[A_HI + hr1 + nt * 4 + t] = hi;
            sm[A_LO + hr1 + nt * 4 + t] = lo;
        }
        // zero pad k=56..63 (words 28..31) for this warp's 16 rows
#pragma unroll
        for (int z = 0; z < 2; z++) {
            int r = w * 16 + (lane >> 1);
            int wd = 28 + (lane & 1) * 2 + z;
            sm[A_HI + r * 36 + wd] = 0;
            sm[A_LO + r * 36 + wd] = 0;
        }
    }
    __syncwarp();

    // ---- layer 2: O[64x32] = H[64x64] @ W2 + b2 ----
    float o[4][4];
#pragma unroll
    for (int nt = 0; nt < 4; nt++) {
        float bb0 = __ldg(&b2[nt * 8 + 2 * t]);
        float bb1 = __ldg(&b2[nt * 8 + 2 * t + 1]);
        o[nt][0] = bb0; o[nt][1] = bb1; o[nt][2] = bb0; o[nt][3] = bb1;
    }
    {
        const int hr0 = (w * 16 + g) * 36;
        const int hr1 = (w * 16 + g + 8) * 36;
#pragma unroll
        for (int ks = 0; ks < 4; ks++) {
            int c0 = ks * 8 + t, c1 = c0 + 4;
            u32 ahi[4], alo[4];
            ahi[0] = sm[A_HI + hr0 + c0]; ahi[1] = sm[A_HI + hr1 + c0];
            ahi[2] = sm[A_HI + hr0 + c1]; ahi[3] = sm[A_HI + hr1 + c1];
            alo[0] = sm[A_LO + hr0 + c0]; alo[1] = sm[A_LO + hr1 + c0];
            alo[2] = sm[A_LO + hr0 + c1]; alo[3] = sm[A_LO + hr1 + c1];
#pragma unroll
            for (int nt = 0; nt < 4; nt++) {
                const u32* w2h = reinterpret_cast<const u32*>(g_w2hi + (nt * 8 + g) * 64);
                const u32* w2l = reinterpret_cast<const u32*>(g_w2lo + (nt * 8 + g) * 64);
                u32 bh0 = __ldg(&w2h[ks * 8 + t]), bh1 = __ldg(&w2h[ks * 8 + t + 4]);
                u32 bl0 = __ldg(&w2l[ks * 8 + t]), bl1 = __ldg(&w2l[ks * 8 + t + 4]);
                mma16816(o[nt], ahi, bh0, bh1);
                mma16816(o[nt], ahi, bl0, bl1);
                mma16816(o[nt], alo, bh0, bh1);
            }
        }
    }

    // ---- LeakyReLU + filtered scatter-max ----
#pragma unroll
    for (int nt = 0; nt < 4; nt++) {
        int ch = nt * 8 + 2 * t;
#pragma unroll
        for (int half = 0; half < 2; half++) {
            int el = w * 16 + g + half * 8;
            if (ebase + el < N_EDGES) {
                int node = scol[el];
                float v0 = o[nt][half * 2 + 0];
                float v1 = o[nt][half * 2 + 1];
                v0 = fmaxf(v0, 0.01f * v0);
                v1 = fmaxf(v1, 0.01f * v1);
                float* p = out + (size_t)node * OUT_CH + ch;
                float c0v = p[0], c1v = p[1];     // monotone max: stale read safe
                if (v0 > c0v) atomicMaxF(p, v0);
                if (v1 > c1v) atomicMaxF(p + 1, v1);
            }
        }
    }
}

// ---------------------------------------------------------------------------
// K2: finalize — -inf -> 0, elementwise max with x
// ---------------------------------------------------------------------------
__global__ void k_final(const float* __restrict__ x, float* __restrict__ out) {
    int i = blockIdx.x * blockDim.x + threadIdx.x;
    if (i >= N_NODES * OUT_CH) return;
    float a = out[i];
    if (__float_as_uint(a) == 0xFF800000u) a = 0.0f;
    out[i] = fmaxf(a, x[i]);
}

// ---------------------------------------------------------------------------
extern "C" void kernel_launch(void* const* d_in, const int* in_sizes, int n_in,
                              void* d_out, int out_size) {
    const float* x         = (const float*)d_in[0];
    const int*   idx32     = (const int*)d_in[1];
    const float* edge_attr = (const float*)d_in[2];
    const float* W1        = (const float*)d_in[3];
    const float* b1        = (const float*)d_in[4];
    const float* W2        = (const float*)d_in[5];
    const float* b2        = (const float*)d_in[6];
    float* out = (float*)d_out;

    k_pre<<<592, 256>>>(x, (const unsigned int*)d_in[1], W1, W2, (unsigned int*)d_out);
    k_edge<<<(N_EDGES + TILE_E - 1) / TILE_E, 128>>>(idx32, edge_attr, b1, b2, out);
    k_final<<<(N_NODES * OUT_CH + 255) / 256, 256>>>(x, out);
}

// round 9
// speedup vs baseline: 1.0836x; 1.0836x over previous
#include <cuda_runtime.h>
#include <cuda_bf16.h>
#include <cstdint>

#define N_NODES 100000
#define N_EDGES 1000000
#define IN_CH   32
#define EDGE_CH 16
#define OUT_CH  32
#define D_MID   56
#define D_CAT   80
#define TILE_E  64
#define NTILES  ((N_EDGES + TILE_E - 1) / TILE_E)

typedef unsigned int u32;

// ---- device globals (no allocation allowed) --------------------------------
static __device__ int g_is64;
static __device__ __align__(16) __nv_bfloat16 g_xhi[N_NODES * IN_CH];
static __device__ __align__(16) __nv_bfloat16 g_xlo[N_NODES * IN_CH];
static __device__ __align__(16) __nv_bfloat16 g_w1hi[D_MID * 88];  // [n][k], stride 88
static __device__ __align__(16) __nv_bfloat16 g_w1lo[D_MID * 88];
static __device__ __align__(16) __nv_bfloat16 g_w2hi[OUT_CH * 64]; // [n][k], k padded 56->64
static __device__ __align__(16) __nv_bfloat16 g_w2lo[OUT_CH * 64];

// ---- helpers ---------------------------------------------------------------
__device__ __forceinline__ void atomicMaxF(float* addr, float val) {
    if (val >= 0.0f) atomicMax(reinterpret_cast<int*>(addr), __float_as_int(val));
    else             atomicMin(reinterpret_cast<unsigned int*>(addr), __float_as_uint(val));
}

__device__ __forceinline__ void mma16816(float d[4], const u32 a[4], u32 b0, u32 b1) {
    asm volatile(
        "mma.sync.aligned.m16n8k16.row.col.f32.bf16.bf16.f32 "
        "{%0,%1,%2,%3}, {%4,%5,%6,%7}, {%8,%9}, {%0,%1,%2,%3};\n"
        : "+f"(d[0]), "+f"(d[1]), "+f"(d[2]), "+f"(d[3])
        : "r"(a[0]), "r"(a[1]), "r"(a[2]), "r"(a[3]), "r"(b0), "r"(b1));
}

// split (v0,v1) into packed bf16x2 hi (return) and lo (out-param)
__device__ __forceinline__ u32 pack_split(float v0, float v1, u32& lo) {
    __nv_bfloat16 h0 = __float2bfloat16(v0), h1 = __float2bfloat16(v1);
    float f0 = __bfloat162float(h0), f1 = __bfloat162float(h1);
    __nv_bfloat16 l0 = __float2bfloat16(v0 - f0), l1 = __float2bfloat16(v1 - f1);
    lo = (u32)__bfloat16_as_ushort(l0) | ((u32)__bfloat16_as_ushort(l1) << 16);
    return (u32)__bfloat16_as_ushort(h0) | ((u32)__bfloat16_as_ushort(h1) << 16);
}

// ---------------------------------------------------------------------------
// K0: init out to -inf, detect int64, prepack x / W1 / W2 into bf16 hi/lo
// ---------------------------------------------------------------------------
__global__ void k_pre(const float* __restrict__ x,
                      const unsigned int* __restrict__ widx,
                      const float* __restrict__ W1,
                      const float* __restrict__ W2,
                      unsigned int* __restrict__ out) {
    if (blockIdx.x == 0) {
        __shared__ int bad;
        if (threadIdx.x == 0) bad = 0;
        __syncthreads();
        for (int i = threadIdx.x; i < 4096; i += blockDim.x)
            if (widx[2 * i + 1] != 0u) bad = 1;   // benign race
        __syncthreads();
        if (threadIdx.x == 0) g_is64 = !bad;
    }
    if (blockIdx.x == 1) {  // W1 [80][56] -> [n][k] hi/lo, stride 88
        for (int i = threadIdx.x; i < D_CAT * D_MID; i += blockDim.x) {
            int k = i / D_MID, n = i % D_MID;
            float v = W1[i];
            __nv_bfloat16 h = __float2bfloat16(v);
            g_w1hi[n * 88 + k] = h;
            g_w1lo[n * 88 + k] = __float2bfloat16(v - __bfloat162float(h));
        }
    }
    if (blockIdx.x == 2) {  // W2 [56][32] -> [n][k pad 64] hi/lo
        for (int i = threadIdx.x; i < OUT_CH * 64; i += blockDim.x) {
            int n = i / 64, k = i % 64;
            float v = (k < D_MID) ? W2[k * OUT_CH + n] : 0.0f;
            __nv_bfloat16 h = __float2bfloat16(v);
            g_w2hi[n * 64 + k] = h;
            g_w2lo[n * 64 + k] = __float2bfloat16(v - __bfloat162float(h));
        }
    }
    int stride = gridDim.x * blockDim.x;
    for (int i = blockIdx.x * blockDim.x + threadIdx.x; i < N_NODES * IN_CH; i += stride) {
        out[i] = 0xFF800000u;  // -inf
        float v = x[i];
        __nv_bfloat16 h = __float2bfloat16(v);
        g_xhi[i] = h;
        g_xlo[i] = __float2bfloat16(v - __bfloat162float(h));
    }
}

// ---------------------------------------------------------------------------
// K1: PERSISTENT tensor-core edge MLP + scatter-max.
// Tile = 64 edges, 4 warps x 16 rows. Weights loaded into smem ONCE per CTA.
// smem word map: A_hi[64x44]@0, A_lo@2816, W1_hi[56x44]@5632, W1_lo@8096.
// H (64x36 words) reuses the A region after a block-wide sync.
// ---------------------------------------------------------------------------
#define A_HI  0
#define A_LO  2816
#define W1_HI 5632
#define W1_LO 8096
#define SMW   10560

__global__ void __launch_bounds__(128) k_edge(const int* __restrict__ idx32,
                                              const float* __restrict__ ea,
                                              const float* __restrict__ b1,
                                              const float* __restrict__ b2,
                                              float* __restrict__ out) {
    __shared__ u32 sm[SMW];
    __shared__ int srol[TILE_E], scol[TILE_E];

    const int tid  = threadIdx.x;
    const int w    = tid >> 5;
    const int lane = tid & 31;
    const int g    = lane >> 2;   // groupID 0..7
    const int t    = lane & 3;    // threadIdInGroup

    // W1 tiles into smem ONCE (prepacked hi/lo)
    {
        const u32* g1h = reinterpret_cast<const u32*>(g_w1hi);
        const u32* g1l = reinterpret_cast<const u32*>(g_w1lo);
        for (int i = tid; i < D_MID * 44; i += 128) {
            sm[W1_HI + i] = g1h[i];
            sm[W1_LO + i] = g1l[i];
        }
    }
    // bias fragments hoisted to registers
    float bb1[7][2], bb2[4][2];
#pragma unroll
    for (int nt = 0; nt < 7; nt++) {
        bb1[nt][0] = __ldg(&b1[nt * 8 + 2 * t]);
        bb1[nt][1] = __ldg(&b1[nt * 8 + 2 * t + 1]);
    }
#pragma unroll
    for (int nt = 0; nt < 4; nt++) {
        bb2[nt][0] = __ldg(&b2[nt * 8 + 2 * t]);
        bb2[nt][1] = __ldg(&b2[nt * 8 + 2 * t + 1]);
    }
    const int is64 = g_is64;

    for (int tile = blockIdx.x; tile < NTILES; tile += gridDim.x) {
        const int ebase = tile * TILE_E;

        __syncthreads();  // previous iteration's smem reads complete
        if (tid < TILE_E) {
            int e = ebase + tid;
            if (e > N_EDGES - 1) e = N_EDGES - 1;
            int r, c;
            if (is64) { r = idx32[2 * e];  c = idx32[2 * (N_EDGES + e)]; }
            else      { r = idx32[e];      c = idx32[N_EDGES + e]; }
            srol[tid] = r; scol[tid] = c;
        }
        __syncthreads();

        // gather x rows (prepacked bf16): 256 row-copies x 4 float4 quads
#pragma unroll
        for (int j = 0; j < 8; j++) {
            int task  = j * 128 + tid;
            int quad  = task & 3;
            int rowid = task >> 2;       // 0..255
            int e     = rowid & 63;
            int sel   = rowid >> 6;      // 0:hi-rol 1:hi-col 2:lo-rol 3:lo-col
            int node  = (sel & 1) ? scol[e] : srol[e];
            const float4* src = reinterpret_cast<const float4*>(
                ((sel < 2) ? g_xhi : g_xlo) + (size_t)node * IN_CH) + quad;
            float4 v = *src;
            u32 off = ((sel < 2) ? A_HI : A_LO) + e * 44 + (sel & 1) * 16 + quad * 4;
            *reinterpret_cast<float4*>(sm + off) = v;
        }
        // edge_attr -> bf16 hi/lo (k cols 64..79)
        {
            __nv_bfloat16* smh = reinterpret_cast<__nv_bfloat16*>(sm);
#pragma unroll
            for (int i = 0; i < 8; i++) {
                int li  = tid + 128 * i;   // 0..1023
                int el  = li >> 4, pos = li & 15;
                float v = (ebase + el < N_EDGES) ? ea[(size_t)(ebase + el) * EDGE_CH + pos] : 0.0f;
                __nv_bfloat16 h = __float2bfloat16(v);
                smh[(u32)(A_HI * 2) + el * 88 + 64 + pos] = h;
                smh[(u32)(A_LO * 2) + el * 88 + 64 + pos] =
                    __float2bfloat16(v - __bfloat162float(h));
            }
        }
        __syncthreads();

        // ---- layer 1: H[64x56] = A[64x80] @ W1 + b1  (3-pass split mma) ----
        float acc[7][4];
#pragma unroll
        for (int nt = 0; nt < 7; nt++) {
            acc[nt][0] = bb1[nt][0]; acc[nt][1] = bb1[nt][1];
            acc[nt][2] = bb1[nt][0]; acc[nt][3] = bb1[nt][1];
        }
        {
            const int ar0 = (w * 16 + g) * 44;
            const int ar1 = (w * 16 + g + 8) * 44;
#pragma unroll
            for (int ks = 0; ks < 5; ks++) {
                int c0 = ks * 8 + t, c1 = c0 + 4;
                u32 ahi[4], alo[4];
                ahi[0] = sm[A_HI + ar0 + c0]; ahi[1] = sm[A_HI + ar1 + c0];
                ahi[2] = sm[A_HI + ar0 + c1]; ahi[3] = sm[A_HI + ar1 + c1];
                alo[0] = sm[A_LO + ar0 + c0]; alo[1] = sm[A_LO + ar1 + c0];
                alo[2] = sm[A_LO + ar0 + c1]; alo[3] = sm[A_LO + ar1 + c1];
#pragma unroll
                for (int nt = 0; nt < 7; nt++) {
                    int bro = (nt * 8 + g) * 44 + ks * 8 + t;
                    u32 bh0 = sm[W1_HI + bro], bh1 = sm[W1_HI + bro + 4];
                    u32 bl0 = sm[W1_LO + bro], bl1 = sm[W1_LO + bro + 4];
                    mma16816(acc[nt], ahi, bh0, bh1);
                    mma16816(acc[nt], ahi, bl0, bl1);
                    mma16816(acc[nt], alo, bh0, bh1);
                }
            }
        }
        __syncthreads();  // everyone done reading A before H overwrites it

        // ---- LeakyReLU(H) -> bf16 hi/lo into smem (stride 36 words) ----
        {
            const int hr0 = (w * 16 + g) * 36;
            const int hr1 = (w * 16 + g + 8) * 36;
#pragma unroll
            for (int nt = 0; nt < 7; nt++) {
                float v0 = acc[nt][0], v1 = acc[nt][1], v2 = acc[nt][2], v3 = acc[nt][3];
                v0 = fmaxf(v0, 0.01f * v0); v1 = fmaxf(v1, 0.01f * v1);
                v2 = fmaxf(v2, 0.01f * v2); v3 = fmaxf(v3, 0.01f * v3);
                u32 lo, hi;
                hi = pack_split(v0, v1, lo);
                sm[A_HI + hr0 + nt * 4 + t] = hi;
                sm[A_LO + hr0 + nt * 4 + t] = lo;
                hi = pack_split(v2, v3, lo);
                sm[A_HI + hr1 + nt * 4 + t] = hi;
                sm[A_LO + hr1 + nt * 4 + t] = lo;
            }
            // zero pad k=56..63 (words 28..31) for this warp's 16 rows
#pragma unroll
            for (int z = 0; z < 2; z++) {
                int r = w * 16 + (lane >> 1);
                int wd = 28 + (lane & 1) * 2 + z;
                sm[A_HI + r * 36 + wd] = 0;
                sm[A_LO + r * 36 + wd] = 0;
            }
        }
        __syncwarp();

        // ---- layer 2: O[64x32] = H[64x64] @ W2 + b2 ----
        float o[4][4];
#pragma unroll
        for (int nt = 0; nt < 4; nt++) {
            o[nt][0] = bb2[nt][0]; o[nt][1] = bb2[nt][1];
            o[nt][2] = bb2[nt][0]; o[nt][3] = bb2[nt][1];
        }
        {
            const int hr0 = (w * 16 + g) * 36;
            const int hr1 = (w * 16 + g + 8) * 36;
#pragma unroll
            for (int ks = 0; ks < 4; ks++) {
                int c0 = ks * 8 + t, c1 = c0 + 4;
                u32 ahi[4], alo[4];
                ahi[0] = sm[A_HI + hr0 + c0]; ahi[1] = sm[A_HI + hr1 + c0];
                ahi[2] = sm[A_HI + hr0 + c1]; ahi[3] = sm[A_HI + hr1 + c1];
                alo[0] = sm[A_LO + hr0 + c0]; alo[1] = sm[A_LO + hr1 + c0];
                alo[2] = sm[A_LO + hr0 + c1]; alo[3] = sm[A_LO + hr1 + c1];
#pragma unroll
                for (int nt = 0; nt < 4; nt++) {
                    const u32* w2h = reinterpret_cast<const u32*>(g_w2hi + (nt * 8 + g) * 64);
                    const u32* w2l = reinterpret_cast<const u32*>(g_w2lo + (nt * 8 + g) * 64);
                    u32 bh0 = __ldg(&w2h[ks * 8 + t]), bh1 = __ldg(&w2h[ks * 8 + t + 4]);
                    u32 bl0 = __ldg(&w2l[ks * 8 + t]), bl1 = __ldg(&w2l[ks * 8 + t + 4]);
                    mma16816(o[nt], ahi, bh0, bh1);
                    mma16816(o[nt], ahi, bl0, bl1);
                    mma16816(o[nt], alo, bh0, bh1);
                }
            }
        }

        // ---- LeakyReLU + filtered scatter-max ----
#pragma unroll
        for (int nt = 0; nt < 4; nt++) {
            int ch = nt * 8 + 2 * t;
#pragma unroll
            for (int half = 0; half < 2; half++) {
                int el = w * 16 + g + half * 8;
                if (ebase + el < N_EDGES) {
                    int node = scol[el];
                    float v0 = o[nt][half * 2 + 0];
                    float v1 = o[nt][half * 2 + 1];
                    v0 = fmaxf(v0, 0.01f * v0);
                    v1 = fmaxf(v1, 0.01f * v1);
                    float* p = out + (size_t)node * OUT_CH + ch;
                    float c0v = p[0], c1v = p[1];     // monotone max: stale read safe
                    if (v0 > c0v) atomicMaxF(p, v0);
                    if (v1 > c1v) atomicMaxF(p + 1, v1);
                }
            }
        }
    }
}

// ---------------------------------------------------------------------------
// K2: finalize — -inf -> 0, elementwise max with x (float4)
// ---------------------------------------------------------------------------
__global__ void k_final(const float4* __restrict__ x, float4* __restrict__ out) {
    int i = blockIdx.x * blockDim.x + threadIdx.x;
    if (i >= N_NODES * OUT_CH / 4) return;
    float4 a = out[i];
    float4 b = x[i];
    if (__float_as_uint(a.x) == 0xFF800000u) a.x = 0.0f;
    if (__float_as_uint(a.y) == 0xFF800000u) a.y = 0.0f;
    if (__float_as_uint(a.z) == 0xFF800000u) a.z = 0.0f;
    if (__float_as_uint(a.w) == 0xFF800000u) a.w = 0.0f;
    a.x = fmaxf(a.x, b.x); a.y = fmaxf(a.y, b.y);
    a.z = fmaxf(a.z, b.z); a.w = fmaxf(a.w, b.w);
    out[i] = a;
}

// ---------------------------------------------------------------------------
extern "C" void kernel_launch(void* const* d_in, const int* in_sizes, int n_in,
                              void* d_out, int out_size) {
    const float* x         = (const float*)d_in[0];
    const int*   idx32     = (const int*)d_in[1];
    const float* edge_attr = (const float*)d_in[2];
    const float* W1        = (const float*)d_in[3];
    const float* b1        = (const float*)d_in[4];
    const float* W2        = (const float*)d_in[5];
    const float* b2        = (const float*)d_in[6];
    float* out = (float*)d_out;

    k_pre<<<592, 256>>>(x, (const unsigned int*)d_in[1], W1, W2, (unsigned int*)d_out);
    k_edge<<<592, 128>>>(idx32, edge_attr, b1, b2, out);
    k_final<<<(N_NODES * OUT_CH / 4 + 255) / 256, 256>>>((const float4*)x, (float4*)out);
}